// round 1
// baseline (speedup 1.0000x reference)
#include <cuda_runtime.h>
#include <math.h>

// ---------------- problem constants ----------------
#define B_    32
#define N_    3136
#define C_    512
#define H_    56
#define NH_   8
#define HD_   64
#define ANUM_ 49
#define SCALE_F 0.125f
#define M_    (B_ * N_)          // 100352

// ---------------- scratch (device globals; no allocation allowed) ----------------
__device__ float g_qkv[(size_t)M_ * 1536];      // [b,n,{q|k|v},c] packed: row stride 1536
__device__ float g_agent[B_ * ANUM_ * C_];      // pooled q: [b,49,512]
__device__ float g_num[B_ * NH_ * ANUM_ * HD_]; // agent_v numerator -> normalized agent_v
__device__ float g_den[B_ * NH_ * ANUM_];       // agent_attn denominators
__device__ float g_out[(size_t)M_ * C_];        // attention out (+ dwc), input to proj

// ---------------- generic SGEMM: C[M,N] = A[M,K] * B[N,K]^T (+bias) ----------------
// 128x128 block tile, BK=16, 256 threads, 8x8 per-thread tile (two 4x4 quads),
// double-buffered smem with register prefetch.
#define BM 128
#define BN 128
#define BK 16

__global__ void __launch_bounds__(256)
sgemm_nt(const float* __restrict__ A, const float* __restrict__ B,
         float* __restrict__ C, const float* __restrict__ bias,
         int K, int lda, int ldb, int ldc)
{
    __shared__ float As[2][BK][BM];
    __shared__ float Bs[2][BK][BN];

    const int tid = threadIdx.x;
    const long bm0 = (long)blockIdx.y * BM;
    const long bn0 = (long)blockIdx.x * BN;
    const int lr = tid >> 2;            // 0..63 (loader row)
    const int lc = (tid & 3) << 2;      // 0,4,8,12 (loader k-col)
    const int ty = tid >> 4;            // 0..15
    const int tx = tid & 15;            // 0..15

    const float* Ap = A + (bm0 + lr) * (long)lda + lc;
    const float* Bp = B + (bn0 + lr) * (long)ldb + lc;

    float acc[8][8];
#pragma unroll
    for (int i = 0; i < 8; ++i)
#pragma unroll
        for (int j = 0; j < 8; ++j) acc[i][j] = 0.f;

    // preload k-tile 0
    {
        float4 a0 = *(const float4*)(Ap);
        float4 a1 = *(const float4*)(Ap + 64l * lda);
        float4 b0 = *(const float4*)(Bp);
        float4 b1 = *(const float4*)(Bp + 64l * ldb);
        As[0][lc+0][lr]    = a0.x; As[0][lc+1][lr]    = a0.y; As[0][lc+2][lr]    = a0.z; As[0][lc+3][lr]    = a0.w;
        As[0][lc+0][lr+64] = a1.x; As[0][lc+1][lr+64] = a1.y; As[0][lc+2][lr+64] = a1.z; As[0][lc+3][lr+64] = a1.w;
        Bs[0][lc+0][lr]    = b0.x; Bs[0][lc+1][lr]    = b0.y; Bs[0][lc+2][lr]    = b0.z; Bs[0][lc+3][lr]    = b0.w;
        Bs[0][lc+0][lr+64] = b1.x; Bs[0][lc+1][lr+64] = b1.y; Bs[0][lc+2][lr+64] = b1.z; Bs[0][lc+3][lr+64] = b1.w;
    }
    __syncthreads();

    const int nkt = K / BK;
    for (int kt = 0; kt < nkt; ++kt) {
        const int cur = kt & 1;
        const bool hasNext = (kt + 1) < nkt;
        float4 a0, a1, b0, b1;
        if (hasNext) {
            const float* Ap2 = Ap + (kt + 1) * BK;
            const float* Bp2 = Bp + (kt + 1) * BK;
            a0 = *(const float4*)(Ap2);
            a1 = *(const float4*)(Ap2 + 64l * lda);
            b0 = *(const float4*)(Bp2);
            b1 = *(const float4*)(Bp2 + 64l * ldb);
        }
#pragma unroll
        for (int k = 0; k < BK; ++k) {
            float4 aA = *(const float4*)&As[cur][k][ty * 4];
            float4 aB = *(const float4*)&As[cur][k][64 + ty * 4];
            float4 bA = *(const float4*)&Bs[cur][k][tx * 4];
            float4 bB = *(const float4*)&Bs[cur][k][64 + tx * 4];
            float ar[8] = {aA.x, aA.y, aA.z, aA.w, aB.x, aB.y, aB.z, aB.w};
            float br[8] = {bA.x, bA.y, bA.z, bA.w, bB.x, bB.y, bB.z, bB.w};
#pragma unroll
            for (int i = 0; i < 8; ++i)
#pragma unroll
                for (int j = 0; j < 8; ++j)
                    acc[i][j] += ar[i] * br[j];
        }
        if (hasNext) {
            __syncthreads();
            const int nb = cur ^ 1;
            As[nb][lc+0][lr]    = a0.x; As[nb][lc+1][lr]    = a0.y; As[nb][lc+2][lr]    = a0.z; As[nb][lc+3][lr]    = a0.w;
            As[nb][lc+0][lr+64] = a1.x; As[nb][lc+1][lr+64] = a1.y; As[nb][lc+2][lr+64] = a1.z; As[nb][lc+3][lr+64] = a1.w;
            Bs[nb][lc+0][lr]    = b0.x; Bs[nb][lc+1][lr]    = b0.y; Bs[nb][lc+2][lr]    = b0.z; Bs[nb][lc+3][lr]    = b0.w;
            Bs[nb][lc+0][lr+64] = b1.x; Bs[nb][lc+1][lr+64] = b1.y; Bs[nb][lc+2][lr+64] = b1.z; Bs[nb][lc+3][lr+64] = b1.w;
            __syncthreads();
        }
    }

    // epilogue
#pragma unroll
    for (int i = 0; i < 2; ++i)
#pragma unroll
        for (int r = 0; r < 4; ++r) {
            long row = bm0 + i * 64 + ty * 4 + r;
            float* Cp = C + row * (long)ldc + bn0;
#pragma unroll
            for (int j = 0; j < 2; ++j) {
                float4 v;
                v.x = acc[i * 4 + r][j * 4 + 0];
                v.y = acc[i * 4 + r][j * 4 + 1];
                v.z = acc[i * 4 + r][j * 4 + 2];
                v.w = acc[i * 4 + r][j * 4 + 3];
                if (bias) {
                    const float* bp = bias + bn0 + j * 64 + tx * 4;
                    v.x += bp[0]; v.y += bp[1]; v.z += bp[2]; v.w += bp[3];
                }
                *(float4*)(Cp + j * 64 + tx * 4) = v;
            }
        }
}

// ---------------- agent pooling: agent[b,p,c] = mean_{8x8} q ----------------
__global__ void pool_q()
{
    const int bp = blockIdx.x;           // b*49+p
    const int b = bp / ANUM_, p = bp % ANUM_;
    const int ph = p / 7, pw = p % 7;
    const int c = threadIdx.x;           // 512 threads
    float s = 0.f;
#pragma unroll
    for (int iy = 0; iy < 8; ++iy)
#pragma unroll
        for (int ix = 0; ix < 8; ++ix) {
            const int n = (ph * 8 + iy) * H_ + pw * 8 + ix;
            s += g_qkv[((size_t)(b * N_ + n)) * 1536 + c];
        }
    g_agent[((size_t)b * ANUM_ + p) * C_ + c] = s * 0.015625f;
}

// ---------------- zero accumulators for agent attention ----------------
__global__ void zero_acc()
{
    const int i = blockIdx.x * 256 + threadIdx.x;
    if (i < B_ * NH_ * ANUM_ * HD_) g_num[i] = 0.f;
    if (i < B_ * NH_ * ANUM_)       g_den[i] = 0.f;
}

// ---------------- agent attention: num[a,c] += exp(SCALE*a.k) * v ; den[a] += exp ----------------
// grid (256 = b*h, 7 n-parts); each block streams 448 tokens in 14 tiles of 32.
__global__ void __launch_bounds__(256)
agent_kv()
{
    const int bh = blockIdx.x;
    const int part = blockIdx.y;
    const int b = bh >> 3, h = bh & 7;

    __shared__ float ag[ANUM_][64];
    __shared__ float Ks[32][68];
    __shared__ float Vs[32][68];
    __shared__ float Ws[ANUM_][33];

    const int tid = threadIdx.x;
    for (int i = tid; i < ANUM_ * 16; i += 256) {
        const int a = i >> 4, c4 = (i & 15) << 2;
        *(float4*)&ag[a][c4] =
            *(const float4*)&g_agent[((size_t)(b * ANUM_ + a)) * C_ + h * HD_ + c4];
    }

    const int cq = tid & 15;     // c block: c = cq*4
    const int a0 = tid >> 4;     // 0..15 ; a = a0 + 16k
    const int nA = (a0 == 0) ? 4 : 3;
    float acc[4][4];
#pragma unroll
    for (int k = 0; k < 4; ++k)
#pragma unroll
        for (int j = 0; j < 4; ++j) acc[k][j] = 0.f;
    float den = 0.f;

    __syncthreads();

    const int n0 = part * 448;
    for (int t = 0; t < 14; ++t) {
        const int nb = n0 + t * 32;
        for (int i = tid; i < 32 * 16; i += 256) {
            const int r = i >> 4, c4 = (i & 15) << 2;
            const size_t base = ((size_t)(b * N_ + nb + r)) * 1536 + h * HD_ + c4;
            *(float4*)&Ks[r][c4] = *(const float4*)&g_qkv[base + 512];
            *(float4*)&Vs[r][c4] = *(const float4*)&g_qkv[base + 1024];
        }
        __syncthreads();

        // phase 1: Ws[a][nt] = exp(SCALE * agent_a . K_nt)
        {
            const int nt = tid & 31;
            const int arr = tid >> 5;    // 0..7
            for (int a = arr; a < ANUM_; a += 8) {
                float s = 0.f;
#pragma unroll
                for (int c4 = 0; c4 < 64; c4 += 4) {
                    float4 av4 = *(const float4*)&ag[a][c4];
                    float4 kv4 = *(const float4*)&Ks[nt][c4];
                    s += av4.x * kv4.x + av4.y * kv4.y + av4.z * kv4.z + av4.w * kv4.w;
                }
                Ws[a][nt] = expf(s * SCALE_F);
            }
        }
        __syncthreads();

        if (tid < ANUM_) {
#pragma unroll
            for (int nt = 0; nt < 32; ++nt) den += Ws[tid][nt];
        }

        // phase 2: acc[a][c4] += Ws[a][nt] * V[nt][c4]
#pragma unroll
        for (int nt = 0; nt < 32; ++nt) {
            const float4 v4 = *(const float4*)&Vs[nt][cq * 4];
#pragma unroll
            for (int k = 0; k < 4; ++k) {
                if (k < 3 || a0 == 0) {
                    const float w = Ws[a0 + 16 * k][nt];
                    acc[k][0] += w * v4.x; acc[k][1] += w * v4.y;
                    acc[k][2] += w * v4.z; acc[k][3] += w * v4.w;
                }
            }
        }
        __syncthreads();
    }

    for (int k = 0; k < nA; ++k) {
        const int a = a0 + 16 * k;
        float* p = &g_num[(((size_t)bh * ANUM_) + a) * HD_ + cq * 4];
        atomicAdd(p + 0, acc[k][0]); atomicAdd(p + 1, acc[k][1]);
        atomicAdd(p + 2, acc[k][2]); atomicAdd(p + 3, acc[k][3]);
    }
    if (tid < ANUM_) atomicAdd(&g_den[bh * ANUM_ + tid], den);
}

// ---------------- normalize: agent_v = num / den (in place) ----------------
__global__ void norm_av()
{
    const int i = blockIdx.x;                 // 32*8*49
    const float inv = 1.f / g_den[i];
    g_num[(size_t)i * HD_ + threadIdx.x] *= inv;
}

// ---------------- q attention: out = softmax(SCALE * q.agent^T) @ agent_v ----------------
// grid (256 = b*h, 25 row-chunks of 128); 1 thread = 1 token row.
__global__ void __launch_bounds__(128)
q_attn()
{
    const int bh = blockIdx.x;
    const int b = bh >> 3, h = bh & 7;
    __shared__ float ag[ANUM_][64];
    __shared__ float av[ANUM_][64];
    const int tid = threadIdx.x;
    for (int i = tid; i < ANUM_ * 16; i += 128) {
        const int a = i >> 4, c4 = (i & 15) << 2;
        *(float4*)&ag[a][c4] = *(const float4*)&g_agent[((size_t)(b * ANUM_ + a)) * C_ + h * HD_ + c4];
        *(float4*)&av[a][c4] = *(const float4*)&g_num[(((size_t)bh * ANUM_) + a) * HD_ + c4];
    }
    __syncthreads();

    const int n = blockIdx.y * 128 + tid;
    if (n >= N_) return;

    float4 q[16];
    const size_t qb = ((size_t)(b * N_ + n)) * 1536 + h * HD_;
#pragma unroll
    for (int i = 0; i < 16; ++i) q[i] = *(const float4*)&g_qkv[qb + 4 * i];

    float4 o[16];
#pragma unroll
    for (int i = 0; i < 16; ++i) { o[i].x = 0.f; o[i].y = 0.f; o[i].z = 0.f; o[i].w = 0.f; }
    float den = 0.f;

    for (int a = 0; a < ANUM_; ++a) {
        float s = 0.f;
#pragma unroll
        for (int i = 0; i < 16; ++i) {
            const float4 k4 = *(const float4*)&ag[a][4 * i];
            s += q[i].x * k4.x + q[i].y * k4.y + q[i].z * k4.z + q[i].w * k4.w;
        }
        const float w = expf(s * SCALE_F);
        den += w;
#pragma unroll
        for (int i = 0; i < 16; ++i) {
            const float4 v4 = *(const float4*)&av[a][4 * i];
            o[i].x += w * v4.x; o[i].y += w * v4.y; o[i].z += w * v4.z; o[i].w += w * v4.w;
        }
    }

    const float inv = 1.f / den;
    float* op = &g_out[((size_t)(b * N_ + n)) * C_ + h * HD_];
#pragma unroll
    for (int i = 0; i < 16; ++i) {
        float4 v;
        v.x = o[i].x * inv; v.y = o[i].y * inv; v.z = o[i].z * inv; v.w = o[i].w * inv;
        *(float4*)&op[4 * i] = v;
    }
}

// ---------------- depthwise 3x3 conv on v, += into g_out (with bias) ----------------
__global__ void __launch_bounds__(256)
dwc_add(const float* __restrict__ w, const float* __restrict__ bias)
{
    __shared__ float ws[C_ * 9];
    __shared__ float bs[C_];
    const int b = blockIdx.x, y = blockIdx.y;
    const int tid = threadIdx.x;
    for (int i = tid; i < C_ * 9; i += 256) ws[i] = w[i];
    for (int i = tid; i < C_; i += 256) bs[i] = bias[i];
    __syncthreads();

    for (int x = 0; x < H_; ++x) {
        for (int c = tid; c < C_; c += 256) {
            float s = bs[c];
#pragma unroll
            for (int ky = 0; ky < 3; ++ky) {
                const int yy = y + ky - 1;
                if (yy < 0 || yy >= H_) continue;
#pragma unroll
                for (int kx = 0; kx < 3; ++kx) {
                    const int xx = x + kx - 1;
                    if (xx < 0 || xx >= H_) continue;
                    s += g_qkv[((size_t)(b * N_ + yy * H_ + xx)) * 1536 + 1024 + c]
                         * ws[c * 9 + ky * 3 + kx];
                }
            }
            g_out[((size_t)(b * N_ + y * H_ + x)) * C_ + c] += s;
        }
    }
}

// ---------------- launch ----------------
extern "C" void kernel_launch(void* const* d_in, const int* in_sizes, int n_in,
                              void* d_out, int out_size)
{
    const float* x      = (const float*)d_in[0];
    const float* qkv_w  = (const float*)d_in[1];
    const float* proj_w = (const float*)d_in[2];
    const float* proj_b = (const float*)d_in[3];
    const float* dwc_w  = (const float*)d_in[4];
    const float* dwc_b  = (const float*)d_in[5];
    float* out = (float*)d_out;

    float *p_qkv = nullptr, *p_out = nullptr;
    cudaGetSymbolAddress((void**)&p_qkv, g_qkv);
    cudaGetSymbolAddress((void**)&p_out, g_out);

    // 1. QKV projection: [100352,512] @ [1536,512]^T -> g_qkv
    sgemm_nt<<<dim3(1536 / BN, M_ / BM), 256>>>(x, qkv_w, p_qkv, nullptr, 512, 512, 512, 1536);
    // 2. zero agent-attn accumulators
    zero_acc<<<(B_ * NH_ * ANUM_ * HD_ + 255) / 256, 256>>>();
    // 3. agent pooling (8x8 mean of q)
    pool_q<<<B_ * ANUM_, C_>>>();
    // 4. agent attention (streaming, no-max softmax, partial sums over 7 n-parts)
    agent_kv<<<dim3(B_ * NH_, 7), 256>>>();
    // 5. normalize agent_v
    norm_av<<<B_ * NH_ * ANUM_, HD_>>>();
    // 6. q attention -> g_out
    q_attn<<<dim3(B_ * NH_, (N_ + 127) / 128), 128>>>();
    // 7. depthwise conv on v, += into g_out
    dwc_add<<<dim3(B_, H_), 256>>>(dwc_w, dwc_b);
    // 8. output projection (+bias) -> d_out
    sgemm_nt<<<dim3(512 / BN, M_ / BM), 256>>>(p_out, proj_w, out, proj_b, 512, 512, 512, 512);
}

// round 6
// speedup vs baseline: 1.9997x; 1.9997x over previous
#include <cuda_runtime.h>
#include <math.h>
#include <stdint.h>

// ---------------- problem constants ----------------
#define B_    32
#define N_    3136
#define C_    512
#define H_    56
#define NH_   8
#define HD_   64
#define ANUM_ 49
#define SCALE_F 0.125f
#define M_    (B_ * N_)          // 100352

// ---------------- scratch ----------------
__device__ float g_qkv[(size_t)M_ * 1536];      // [b,n,{q|k|v},c]
__device__ float g_agent[B_ * ANUM_ * C_];
__device__ float g_num[B_ * NH_ * ANUM_ * HD_];
__device__ float g_den[B_ * NH_ * ANUM_];
__device__ float g_out[(size_t)M_ * C_];

// ---------------- tf32 helpers ----------------
__device__ __forceinline__ float f2tf(float x) {
    uint32_t u;
    asm("cvt.rna.tf32.f32 %0, %1;" : "=r"(u) : "f"(x));
    return __uint_as_float(u);
}

__device__ __forceinline__ void mma_tf32(float* c, const uint32_t* a, const uint32_t* b) {
    asm volatile(
        "mma.sync.aligned.m16n8k8.row.col.f32.tf32.tf32.f32 "
        "{%0,%1,%2,%3}, {%4,%5,%6,%7}, {%8,%9}, {%0,%1,%2,%3};\n"
        : "+f"(c[0]), "+f"(c[1]), "+f"(c[2]), "+f"(c[3])
        : "r"(a[0]), "r"(a[1]), "r"(a[2]), "r"(a[3]), "r"(b[0]), "r"(b[1]));
}

// ---------------- tensor-core GEMM via mma.sync tf32 ----------------
// C[M,N] = A[M,K] * B[N,K]^T (+bias). 128x128 tile, BK=16, 8 warps (2x4),
// warp tile 64x32 (4x4 m16n8k8 frags). smem [row][16+4] is conflict-free
// for the fragment load pattern. Register-prefetch double buffer.
#define ASTR 20

__global__ void __launch_bounds__(256)
gemm_mma(const float* __restrict__ A, const float* __restrict__ Bw,
         float* __restrict__ C, const float* __restrict__ bias,
         int K, int lda, int ldb, int ldc)
{
    __shared__ float As[2][128][ASTR];
    __shared__ float Bs[2][128][ASTR];
    __shared__ float bsh[128];

    const int tid = threadIdx.x;
    const int wid = tid >> 5, lane = tid & 31;
    const int g = lane >> 2, t = lane & 3;
    const int wm = (wid >> 2) * 64;          // warp M offset
    const int wn = (wid & 3) * 32;           // warp N offset
    const long bm0 = (long)blockIdx.y * 128;
    const long bn0 = (long)blockIdx.x * 128;

    const int lr = tid >> 2;                 // loader row 0..63 (+64 for 2nd)
    const int lj = tid & 3;                  // 16B chunk 0..3

    if (tid < 128) bsh[tid] = bias ? bias[bn0 + tid] : 0.f;

    const float* Ap = A + (bm0 + lr) * (long)lda + lj * 4;
    const float* Bp = Bw + (bn0 + lr) * (long)ldb + lj * 4;
    const long a64 = 64l * lda, b64 = 64l * ldb;

    float acc[4][4][4];
#pragma unroll
    for (int i = 0; i < 4; ++i)
#pragma unroll
        for (int j = 0; j < 4; ++j)
#pragma unroll
            for (int q = 0; q < 4; ++q) acc[i][j][q] = 0.f;

    float4 pa0, pa1, pb0, pb1;
    // prologue: load stage 0
    pa0 = *(const float4*)(Ap);
    pa1 = *(const float4*)(Ap + a64);
    pb0 = *(const float4*)(Bp);
    pb1 = *(const float4*)(Bp + b64);
    {
        float4 v;
        v.x = f2tf(pa0.x); v.y = f2tf(pa0.y); v.z = f2tf(pa0.z); v.w = f2tf(pa0.w);
        *(float4*)&As[0][lr][lj * 4] = v;
        v.x = f2tf(pa1.x); v.y = f2tf(pa1.y); v.z = f2tf(pa1.z); v.w = f2tf(pa1.w);
        *(float4*)&As[0][lr + 64][lj * 4] = v;
        v.x = f2tf(pb0.x); v.y = f2tf(pb0.y); v.z = f2tf(pb0.z); v.w = f2tf(pb0.w);
        *(float4*)&Bs[0][lr][lj * 4] = v;
        v.x = f2tf(pb1.x); v.y = f2tf(pb1.y); v.z = f2tf(pb1.z); v.w = f2tf(pb1.w);
        *(float4*)&Bs[0][lr + 64][lj * 4] = v;
    }
    __syncthreads();

    const int nkt = K / 16;
    for (int kt = 0; kt < nkt; ++kt) {
        const int cur = kt & 1;
        const bool hasNext = (kt + 1) < nkt;
        if (hasNext) {
            const float* Ap2 = Ap + (kt + 1) * 16;
            const float* Bp2 = Bp + (kt + 1) * 16;
            pa0 = *(const float4*)(Ap2);
            pa1 = *(const float4*)(Ap2 + a64);
            pb0 = *(const float4*)(Bp2);
            pb1 = *(const float4*)(Bp2 + b64);
        }

#pragma unroll
        for (int ks = 0; ks < 16; ks += 8) {
            uint32_t af[4][4], bf[4][2];
#pragma unroll
            for (int mf = 0; mf < 4; ++mf) {
                const int row = wm + mf * 16 + g;
                af[mf][0] = __float_as_uint(As[cur][row][ks + t]);
                af[mf][1] = __float_as_uint(As[cur][row + 8][ks + t]);
                af[mf][2] = __float_as_uint(As[cur][row][ks + t + 4]);
                af[mf][3] = __float_as_uint(As[cur][row + 8][ks + t + 4]);
            }
#pragma unroll
            for (int nf = 0; nf < 4; ++nf) {
                const int col = wn + nf * 8 + g;
                bf[nf][0] = __float_as_uint(Bs[cur][col][ks + t]);
                bf[nf][1] = __float_as_uint(Bs[cur][col][ks + t + 4]);
            }
#pragma unroll
            for (int mf = 0; mf < 4; ++mf)
#pragma unroll
                for (int nf = 0; nf < 4; ++nf)
                    mma_tf32(acc[mf][nf], af[mf], bf[nf]);
        }

        if (hasNext) {
            const int nb = cur ^ 1;
            float4 v;
            v.x = f2tf(pa0.x); v.y = f2tf(pa0.y); v.z = f2tf(pa0.z); v.w = f2tf(pa0.w);
            *(float4*)&As[nb][lr][lj * 4] = v;
            v.x = f2tf(pa1.x); v.y = f2tf(pa1.y); v.z = f2tf(pa1.z); v.w = f2tf(pa1.w);
            *(float4*)&As[nb][lr + 64][lj * 4] = v;
            v.x = f2tf(pb0.x); v.y = f2tf(pb0.y); v.z = f2tf(pb0.z); v.w = f2tf(pb0.w);
            *(float4*)&Bs[nb][lr][lj * 4] = v;
            v.x = f2tf(pb1.x); v.y = f2tf(pb1.y); v.z = f2tf(pb1.z); v.w = f2tf(pb1.w);
            *(float4*)&Bs[nb][lr + 64][lj * 4] = v;
            __syncthreads();
        }
    }

    // epilogue: c0/c1 at (row, 2t), (row, 2t+1); c2/c3 at row+8
#pragma unroll
    for (int mf = 0; mf < 4; ++mf) {
        const long row = bm0 + wm + mf * 16 + g;
#pragma unroll
        for (int nf = 0; nf < 4; ++nf) {
            const int col = wn + nf * 8 + 2 * t;
            float2 v0, v1;
            v0.x = acc[mf][nf][0] + bsh[col];
            v0.y = acc[mf][nf][1] + bsh[col + 1];
            v1.x = acc[mf][nf][2] + bsh[col];
            v1.y = acc[mf][nf][3] + bsh[col + 1];
            *(float2*)(C + row * (long)ldc + bn0 + col) = v0;
            *(float2*)(C + (row + 8) * (long)ldc + bn0 + col) = v1;
        }
    }
}

// ---------------- agent pooling ----------------
__global__ void pool_q()
{
    const int bp = blockIdx.x;
    const int b = bp / ANUM_, p = bp % ANUM_;
    const int ph = p / 7, pw = p % 7;
    const int c = threadIdx.x;
    float s = 0.f;
#pragma unroll
    for (int iy = 0; iy < 8; ++iy)
#pragma unroll
        for (int ix = 0; ix < 8; ++ix) {
            const int n = (ph * 8 + iy) * H_ + pw * 8 + ix;
            s += g_qkv[((size_t)(b * N_ + n)) * 1536 + c];
        }
    g_agent[((size_t)b * ANUM_ + p) * C_ + c] = s * 0.015625f;
}

__global__ void zero_acc()
{
    const int i = blockIdx.x * 256 + threadIdx.x;
    if (i < B_ * NH_ * ANUM_ * HD_) g_num[i] = 0.f;
    if (i < B_ * NH_ * ANUM_)       g_den[i] = 0.f;
}

// ---------------- agent attention ----------------
__global__ void __launch_bounds__(256)
agent_kv()
{
    const int bh = blockIdx.x;
    const int part = blockIdx.y;
    const int b = bh >> 3, h = bh & 7;

    __shared__ float ag[ANUM_][64];
    __shared__ float Ks[32][68];
    __shared__ float Vs[32][68];
    __shared__ float Ws[ANUM_][33];

    const int tid = threadIdx.x;
    for (int i = tid; i < ANUM_ * 16; i += 256) {
        const int a = i >> 4, c4 = (i & 15) << 2;
        *(float4*)&ag[a][c4] =
            *(const float4*)&g_agent[((size_t)(b * ANUM_ + a)) * C_ + h * HD_ + c4];
    }

    const int cq = tid & 15;
    const int a0 = tid >> 4;
    const int nA = (a0 == 0) ? 4 : 3;
    float acc[4][4];
#pragma unroll
    for (int k = 0; k < 4; ++k)
#pragma unroll
        for (int j = 0; j < 4; ++j) acc[k][j] = 0.f;
    float den = 0.f;

    __syncthreads();

    const int n0 = part * 448;
    for (int t = 0; t < 14; ++t) {
        const int nb = n0 + t * 32;
        for (int i = tid; i < 32 * 16; i += 256) {
            const int r = i >> 4, c4 = (i & 15) << 2;
            const size_t base = ((size_t)(b * N_ + nb + r)) * 1536 + h * HD_ + c4;
            *(float4*)&Ks[r][c4] = *(const float4*)&g_qkv[base + 512];
            *(float4*)&Vs[r][c4] = *(const float4*)&g_qkv[base + 1024];
        }
        __syncthreads();

        {
            const int nt = tid & 31;
            const int arr = tid >> 5;
            for (int a = arr; a < ANUM_; a += 8) {
                float s = 0.f;
#pragma unroll
                for (int c4 = 0; c4 < 64; c4 += 4) {
                    float4 av4 = *(const float4*)&ag[a][c4];
                    float4 kv4 = *(const float4*)&Ks[nt][c4];
                    s += av4.x * kv4.x + av4.y * kv4.y + av4.z * kv4.z + av4.w * kv4.w;
                }
                Ws[a][nt] = expf(s * SCALE_F);
            }
        }
        __syncthreads();

        if (tid < ANUM_) {
#pragma unroll
            for (int nt = 0; nt < 32; ++nt) den += Ws[tid][nt];
        }

#pragma unroll
        for (int nt = 0; nt < 32; ++nt) {
            const float4 v4 = *(const float4*)&Vs[nt][cq * 4];
#pragma unroll
            for (int k = 0; k < 4; ++k) {
                if (k < 3 || a0 == 0) {
                    const float w = Ws[a0 + 16 * k][nt];
                    acc[k][0] += w * v4.x; acc[k][1] += w * v4.y;
                    acc[k][2] += w * v4.z; acc[k][3] += w * v4.w;
                }
            }
        }
        __syncthreads();
    }

    for (int k = 0; k < nA; ++k) {
        const int a = a0 + 16 * k;
        float* p = &g_num[(((size_t)bh * ANUM_) + a) * HD_ + cq * 4];
        atomicAdd(p + 0, acc[k][0]); atomicAdd(p + 1, acc[k][1]);
        atomicAdd(p + 2, acc[k][2]); atomicAdd(p + 3, acc[k][3]);
    }
    if (tid < ANUM_) atomicAdd(&g_den[bh * ANUM_ + tid], den);
}

__global__ void norm_av()
{
    const int i = blockIdx.x;
    const float inv = 1.f / g_den[i];
    g_num[(size_t)i * HD_ + threadIdx.x] *= inv;
}

// ---------------- q attention ----------------
__global__ void __launch_bounds__(128)
q_attn()
{
    const int bh = blockIdx.x;
    const int b = bh >> 3, h = bh & 7;
    __shared__ float ag[ANUM_][64];
    __shared__ float av[ANUM_][64];
    const int tid = threadIdx.x;
    for (int i = tid; i < ANUM_ * 16; i += 128) {
        const int a = i >> 4, c4 = (i & 15) << 2;
        *(float4*)&ag[a][c4] = *(const float4*)&g_agent[((size_t)(b * ANUM_ + a)) * C_ + h * HD_ + c4];
        *(float4*)&av[a][c4] = *(const float4*)&g_num[(((size_t)bh * ANUM_) + a) * HD_ + c4];
    }
    __syncthreads();

    const int n = blockIdx.y * 128 + tid;
    if (n >= N_) return;

    float4 q[16];
    const size_t qb = ((size_t)(b * N_ + n)) * 1536 + h * HD_;
#pragma unroll
    for (int i = 0; i < 16; ++i) q[i] = *(const float4*)&g_qkv[qb + 4 * i];

    float4 o[16];
#pragma unroll
    for (int i = 0; i < 16; ++i) { o[i].x = 0.f; o[i].y = 0.f; o[i].z = 0.f; o[i].w = 0.f; }
    float den = 0.f;

    for (int a = 0; a < ANUM_; ++a) {
        float s = 0.f;
#pragma unroll
        for (int i = 0; i < 16; ++i) {
            const float4 k4 = *(const float4*)&ag[a][4 * i];
            s += q[i].x * k4.x + q[i].y * k4.y + q[i].z * k4.z + q[i].w * k4.w;
        }
        const float w = expf(s * SCALE_F);
        den += w;
#pragma unroll
        for (int i = 0; i < 16; ++i) {
            const float4 v4 = *(const float4*)&av[a][4 * i];
            o[i].x += w * v4.x; o[i].y += w * v4.y; o[i].z += w * v4.z; o[i].w += w * v4.w;
        }
    }

    const float inv = 1.f / den;
    float* op = &g_out[((size_t)(b * N_ + n)) * C_ + h * HD_];
#pragma unroll
    for (int i = 0; i < 16; ++i) {
        float4 v;
        v.x = o[i].x * inv; v.y = o[i].y * inv; v.z = o[i].z * inv; v.w = o[i].w * inv;
        *(float4*)&op[4 * i] = v;
    }
}

// ---------------- depthwise 3x3 conv ----------------
__global__ void __launch_bounds__(256)
dwc_add(const float* __restrict__ w, const float* __restrict__ bias)
{
    __shared__ float ws[C_ * 9];
    __shared__ float bs[C_];
    const int b = blockIdx.x, y = blockIdx.y;
    const int tid = threadIdx.x;
    for (int i = tid; i < C_ * 9; i += 256) ws[i] = w[i];
    for (int i = tid; i < C_; i += 256) bs[i] = bias[i];
    __syncthreads();

    for (int x = 0; x < H_; ++x) {
        for (int c = tid; c < C_; c += 256) {
            float s = bs[c];
#pragma unroll
            for (int ky = 0; ky < 3; ++ky) {
                const int yy = y + ky - 1;
                if (yy < 0 || yy >= H_) continue;
#pragma unroll
                for (int kx = 0; kx < 3; ++kx) {
                    const int xx = x + kx - 1;
                    if (xx < 0 || xx >= H_) continue;
                    s += g_qkv[((size_t)(b * N_ + yy * H_ + xx)) * 1536 + 1024 + c]
                         * ws[c * 9 + ky * 3 + kx];
                }
            }
            g_out[((size_t)(b * N_ + y * H_ + x)) * C_ + c] += s;
        }
    }
}

// ---------------- launch ----------------
extern "C" void kernel_launch(void* const* d_in, const int* in_sizes, int n_in,
                              void* d_out, int out_size)
{
    const float* x      = (const float*)d_in[0];
    const float* qkv_w  = (const float*)d_in[1];
    const float* proj_w = (const float*)d_in[2];
    const float* proj_b = (const float*)d_in[3];
    const float* dwc_w  = (const float*)d_in[4];
    const float* dwc_b  = (const float*)d_in[5];
    float* out = (float*)d_out;

    float *p_qkv = nullptr, *p_out = nullptr;
    cudaGetSymbolAddress((void**)&p_qkv, g_qkv);
    cudaGetSymbolAddress((void**)&p_out, g_out);

    // 1. QKV projection: [100352,512] @ [1536,512]^T -> g_qkv
    gemm_mma<<<dim3(1536 / 128, M_ / 128), 256>>>(x, qkv_w, p_qkv, nullptr, 512, 512, 512, 1536);
    // 2. zero agent-attn accumulators
    zero_acc<<<(B_ * NH_ * ANUM_ * HD_ + 255) / 256, 256>>>();
    // 3. agent pooling
    pool_q<<<B_ * ANUM_, C_>>>();
    // 4. agent attention
    agent_kv<<<dim3(B_ * NH_, 7), 256>>>();
    // 5. normalize agent_v
    norm_av<<<B_ * NH_ * ANUM_, HD_>>>();
    // 6. q attention -> g_out
    q_attn<<<dim3(B_ * NH_, (N_ + 127) / 128), 128>>>();
    // 7. depthwise conv on v, += into g_out
    dwc_add<<<dim3(B_, H_), 256>>>(dwc_w, dwc_b);
    // 8. output projection (+bias) -> d_out
    gemm_mma<<<dim3(512 / 128, M_ / 128), 256>>>(p_out, proj_w, out, proj_b, 512, 512, 512, 512);
}

// round 7
// speedup vs baseline: 2.0951x; 1.0478x over previous
#include <cuda_runtime.h>
#include <math.h>
#include <stdint.h>

// ---------------- problem constants ----------------
#define B_    32
#define N_    3136
#define C_    512
#define H_    56
#define NH_   8
#define HD_   64
#define ANUM_ 49
#define SCALE_F 0.125f
#define M_    (B_ * N_)          // 100352

// ---------------- scratch ----------------
__device__ float g_qkv[(size_t)M_ * 1536];      // [b,n,{q|k|v},c]
__device__ float g_agent[B_ * ANUM_ * C_];
__device__ float g_num[B_ * NH_ * ANUM_ * HD_];
__device__ float g_den[B_ * NH_ * ANUM_];
__device__ float g_out[(size_t)M_ * C_];        // tf32(x) scratch, then attn+dwc out
__device__ float g_w[1536 * 512 + 512 * 512];   // tf32 qkv_w | proj_w

// ---------------- tf32 helpers ----------------
__device__ __forceinline__ float f2tf(float x) {
    uint32_t u;
    asm("cvt.rna.tf32.f32 %0, %1;" : "=r"(u) : "f"(x));
    return __uint_as_float(u);
}

__device__ __forceinline__ void mma_tf32(float* c, const uint32_t* a, const uint32_t* b) {
    asm volatile(
        "mma.sync.aligned.m16n8k8.row.col.f32.tf32.tf32.f32 "
        "{%0,%1,%2,%3}, {%4,%5,%6,%7}, {%8,%9}, {%0,%1,%2,%3};\n"
        : "+f"(c[0]), "+f"(c[1]), "+f"(c[2]), "+f"(c[3])
        : "r"(a[0]), "r"(a[1]), "r"(a[2]), "r"(a[3]), "r"(b[0]), "r"(b[1]));
}

__device__ __forceinline__ uint32_t smem_u32(const void* p) {
    uint32_t a;
    asm("{ .reg .u64 t; cvta.to.shared.u64 t, %1; cvt.u32.u64 %0, t; }" : "=r"(a) : "l"(p));
    return a;
}

__device__ __forceinline__ void cp16(uint32_t dst, const void* src) {
    asm volatile("cp.async.cg.shared.global [%0], [%1], 16;" :: "r"(dst), "l"(src));
}

// ---------------- tf32 pre-convert ----------------
__global__ void cvt_tf32(const float* __restrict__ src, float* __restrict__ dst, int n4)
{
    const int i = blockIdx.x * 256 + threadIdx.x;
    if (i < n4) {
        float4 v = ((const float4*)src)[i];
        v.x = f2tf(v.x); v.y = f2tf(v.y); v.z = f2tf(v.z); v.w = f2tf(v.w);
        ((float4*)dst)[i] = v;
    }
}

// ---------------- pipelined tensor-core GEMM (inputs pre-rounded to tf32) ----------
// C[M,N] = A[M,K] * B[N,K]^T (+bias). 128x128 tile, BK=16, 3-stage cp.async ring,
// 8 warps (2x4), warp tile 64x32 (4x4 m16n8k8 frags), padded smem stride 20.
#define ASTR 20
#define G3_SMEM ((6 * 128 * ASTR + 128) * 4)   // 3x(A+B) stages + bias

__global__ void __launch_bounds__(256)
gemm_mma3(const float* __restrict__ A, const float* __restrict__ Bw,
          float* __restrict__ C, const float* __restrict__ bias,
          int K, int lda, int ldb, int ldc)
{
    extern __shared__ float smem[];
    float (*As)[128][ASTR] = (float(*)[128][ASTR])smem;
    float (*Bs)[128][ASTR] = (float(*)[128][ASTR])(smem + 3 * 128 * ASTR);
    float* bsh = smem + 6 * 128 * ASTR;

    const uint32_t aBase = smem_u32(smem);
    const uint32_t bBase = aBase + 3 * 128 * ASTR * 4;

    const int tid = threadIdx.x;
    const int wid = tid >> 5, lane = tid & 31;
    const int g = lane >> 2, t = lane & 3;
    const int wm = (wid >> 2) * 64;
    const int wn = (wid & 3) * 32;
    const long bm0 = (long)blockIdx.y * 128;
    const long bn0 = (long)blockIdx.x * 128;
    const int lr = tid >> 2;
    const int lj = tid & 3;

    if (tid < 128) bsh[tid] = bias ? bias[bn0 + tid] : 0.f;

    const float* Ag = A + (bm0 + lr) * (long)lda + lj * 4;
    const float* Bg = Bw + (bn0 + lr) * (long)ldb + lj * 4;
    const long a64 = 64l * lda, b64 = 64l * ldb;
    const uint32_t soff = (uint32_t)(lr * ASTR + lj * 4) * 4;

    auto load_stage = [&](int s) {
        const int buf = s % 3;
        const float* Ap = Ag + s * 16;
        const float* Bp = Bg + s * 16;
        const uint32_t bofs = (uint32_t)(buf * 128 * ASTR * 4) + soff;
        cp16(aBase + bofs, Ap);
        cp16(aBase + bofs + 64u * ASTR * 4, Ap + a64);
        cp16(bBase + bofs, Bp);
        cp16(bBase + bofs + 64u * ASTR * 4, Bp + b64);
        asm volatile("cp.async.commit_group;" ::: "memory");
    };

    float acc[4][4][4];
#pragma unroll
    for (int i = 0; i < 4; ++i)
#pragma unroll
        for (int j = 0; j < 4; ++j)
#pragma unroll
            for (int q = 0; q < 4; ++q) acc[i][j][q] = 0.f;

    const int nkt = K / 16;
    load_stage(0);
    load_stage(1);

    for (int kt = 0; kt < nkt; ++kt) {
        asm volatile("cp.async.wait_group 1;" ::: "memory");
        __syncthreads();
        const int cur = kt % 3;

#pragma unroll
        for (int ks = 0; ks < 16; ks += 8) {
            uint32_t af[4][4], bf[4][2];
#pragma unroll
            for (int mf = 0; mf < 4; ++mf) {
                const int row = wm + mf * 16 + g;
                af[mf][0] = __float_as_uint(As[cur][row][ks + t]);
                af[mf][1] = __float_as_uint(As[cur][row + 8][ks + t]);
                af[mf][2] = __float_as_uint(As[cur][row][ks + t + 4]);
                af[mf][3] = __float_as_uint(As[cur][row + 8][ks + t + 4]);
            }
#pragma unroll
            for (int nf = 0; nf < 4; ++nf) {
                const int col = wn + nf * 8 + g;
                bf[nf][0] = __float_as_uint(Bs[cur][col][ks + t]);
                bf[nf][1] = __float_as_uint(Bs[cur][col][ks + t + 4]);
            }
#pragma unroll
            for (int mf = 0; mf < 4; ++mf)
#pragma unroll
                for (int nf = 0; nf < 4; ++nf)
                    mma_tf32(acc[mf][nf], af[mf], bf[nf]);
        }

        if (kt + 2 < nkt) load_stage(kt + 2);
        else asm volatile("cp.async.commit_group;" ::: "memory");
    }

    // epilogue
#pragma unroll
    for (int mf = 0; mf < 4; ++mf) {
        const long row = bm0 + wm + mf * 16 + g;
#pragma unroll
        for (int nf = 0; nf < 4; ++nf) {
            const int col = wn + nf * 8 + 2 * t;
            float2 v0, v1;
            v0.x = acc[mf][nf][0] + bsh[col];
            v0.y = acc[mf][nf][1] + bsh[col + 1];
            v1.x = acc[mf][nf][2] + bsh[col];
            v1.y = acc[mf][nf][3] + bsh[col + 1];
            *(float2*)(C + row * (long)ldc + bn0 + col) = v0;
            *(float2*)(C + (row + 8) * (long)ldc + bn0 + col) = v1;
        }
    }
}

// ---------------- agent pooling ----------------
__global__ void pool_q()
{
    const int bp = blockIdx.x;
    const int b = bp / ANUM_, p = bp % ANUM_;
    const int ph = p / 7, pw = p % 7;
    const int c = threadIdx.x;
    float s = 0.f;
#pragma unroll
    for (int iy = 0; iy < 8; ++iy)
#pragma unroll
        for (int ix = 0; ix < 8; ++ix) {
            const int n = (ph * 8 + iy) * H_ + pw * 8 + ix;
            s += g_qkv[((size_t)(b * N_ + n)) * 1536 + c];
        }
    g_agent[((size_t)b * ANUM_ + p) * C_ + c] = s * 0.015625f;
}

__global__ void zero_acc()
{
    const int i = blockIdx.x * 256 + threadIdx.x;
    if (i < B_ * NH_ * ANUM_ * HD_) g_num[i] = 0.f;
    if (i < B_ * NH_ * ANUM_)       g_den[i] = 0.f;
}

// ---------------- agent attention ----------------
__global__ void __launch_bounds__(256)
agent_kv()
{
    const int bh = blockIdx.x;
    const int part = blockIdx.y;
    const int b = bh >> 3, h = bh & 7;

    __shared__ float ag[ANUM_][64];
    __shared__ float Ks[32][68];
    __shared__ float Vs[32][68];
    __shared__ float Ws[ANUM_][33];

    const int tid = threadIdx.x;
    for (int i = tid; i < ANUM_ * 16; i += 256) {
        const int a = i >> 4, c4 = (i & 15) << 2;
        *(float4*)&ag[a][c4] =
            *(const float4*)&g_agent[((size_t)(b * ANUM_ + a)) * C_ + h * HD_ + c4];
    }

    const int cq = tid & 15;
    const int a0 = tid >> 4;
    const int nA = (a0 == 0) ? 4 : 3;
    float acc[4][4];
#pragma unroll
    for (int k = 0; k < 4; ++k)
#pragma unroll
        for (int j = 0; j < 4; ++j) acc[k][j] = 0.f;
    float den = 0.f;

    __syncthreads();

    const int n0 = part * 448;
    for (int t = 0; t < 14; ++t) {
        const int nb = n0 + t * 32;
        for (int i = tid; i < 32 * 16; i += 256) {
            const int r = i >> 4, c4 = (i & 15) << 2;
            const size_t base = ((size_t)(b * N_ + nb + r)) * 1536 + h * HD_ + c4;
            *(float4*)&Ks[r][c4] = *(const float4*)&g_qkv[base + 512];
            *(float4*)&Vs[r][c4] = *(const float4*)&g_qkv[base + 1024];
        }
        __syncthreads();

        {
            const int nt = tid & 31;
            const int arr = tid >> 5;
            for (int a = arr; a < ANUM_; a += 8) {
                float s = 0.f;
#pragma unroll
                for (int c4 = 0; c4 < 64; c4 += 4) {
                    float4 av4 = *(const float4*)&ag[a][c4];
                    float4 kv4 = *(const float4*)&Ks[nt][c4];
                    s += av4.x * kv4.x + av4.y * kv4.y + av4.z * kv4.z + av4.w * kv4.w;
                }
                Ws[a][nt] = expf(s * SCALE_F);
            }
        }
        __syncthreads();

        if (tid < ANUM_) {
#pragma unroll
            for (int nt = 0; nt < 32; ++nt) den += Ws[tid][nt];
        }

#pragma unroll
        for (int nt = 0; nt < 32; ++nt) {
            const float4 v4 = *(const float4*)&Vs[nt][cq * 4];
#pragma unroll
            for (int k = 0; k < 4; ++k) {
                if (k < 3 || a0 == 0) {
                    const float w = Ws[a0 + 16 * k][nt];
                    acc[k][0] += w * v4.x; acc[k][1] += w * v4.y;
                    acc[k][2] += w * v4.z; acc[k][3] += w * v4.w;
                }
            }
        }
        __syncthreads();
    }

    for (int k = 0; k < nA; ++k) {
        const int a = a0 + 16 * k;
        float* p = &g_num[(((size_t)bh * ANUM_) + a) * HD_ + cq * 4];
        atomicAdd(p + 0, acc[k][0]); atomicAdd(p + 1, acc[k][1]);
        atomicAdd(p + 2, acc[k][2]); atomicAdd(p + 3, acc[k][3]);
    }
    if (tid < ANUM_) atomicAdd(&g_den[bh * ANUM_ + tid], den);
}

__global__ void norm_av()
{
    const int i = blockIdx.x;
    const float inv = 1.f / g_den[i];
    g_num[(size_t)i * HD_ + threadIdx.x] *= inv;
}

// ---------------- q attention + fused depthwise conv ----------------
// out[n, h*64+c] = softmax(SCALE q . ag^T) @ av  +  dwc(v)[n,c] + dwc_b
// stored tf32-rounded (proj GEMM input needs no further conversion).
__global__ void __launch_bounds__(128)
q_attn_dwc(const float* __restrict__ dwcw, const float* __restrict__ dwcb)
{
    const int bh = blockIdx.x;
    const int b = bh >> 3, h = bh & 7;
    __shared__ float ag[ANUM_][64];
    __shared__ float av[ANUM_][64];
    __shared__ float ws[64][9];
    __shared__ float wb[64];
    const int tid = threadIdx.x;
    for (int i = tid; i < ANUM_ * 16; i += 128) {
        const int a = i >> 4, c4 = (i & 15) << 2;
        *(float4*)&ag[a][c4] = *(const float4*)&g_agent[((size_t)(b * ANUM_ + a)) * C_ + h * HD_ + c4];
        *(float4*)&av[a][c4] = *(const float4*)&g_num[(((size_t)bh * ANUM_) + a) * HD_ + c4];
    }
    for (int i = tid; i < 64 * 9; i += 128) ws[i / 9][i % 9] = dwcw[(h * 64 + i / 9) * 9 + i % 9];
    if (tid < 64) wb[tid] = dwcb[h * 64 + tid];
    __syncthreads();

    const int n = blockIdx.y * 128 + tid;
    if (n >= N_) return;

    float4 q[16];
    const size_t qb = ((size_t)(b * N_ + n)) * 1536 + h * HD_;
#pragma unroll
    for (int i = 0; i < 16; ++i) q[i] = *(const float4*)&g_qkv[qb + 4 * i];

    float4 o[16];
#pragma unroll
    for (int i = 0; i < 16; ++i) { o[i].x = 0.f; o[i].y = 0.f; o[i].z = 0.f; o[i].w = 0.f; }
    float den = 0.f;

    for (int a = 0; a < ANUM_; ++a) {
        float s = 0.f;
#pragma unroll
        for (int i = 0; i < 16; ++i) {
            const float4 k4 = *(const float4*)&ag[a][4 * i];
            s += q[i].x * k4.x + q[i].y * k4.y + q[i].z * k4.z + q[i].w * k4.w;
        }
        const float w = expf(s * SCALE_F);
        den += w;
#pragma unroll
        for (int i = 0; i < 16; ++i) {
            const float4 v4 = *(const float4*)&av[a][4 * i];
            o[i].x += w * v4.x; o[i].y += w * v4.y; o[i].z += w * v4.z; o[i].w += w * v4.w;
        }
    }

    const float inv = 1.f / den;
#pragma unroll
    for (int i = 0; i < 16; ++i) {
        o[i].x = o[i].x * inv + wb[4 * i + 0];
        o[i].y = o[i].y * inv + wb[4 * i + 1];
        o[i].z = o[i].z * inv + wb[4 * i + 2];
        o[i].w = o[i].w * inv + wb[4 * i + 3];
    }

    // depthwise 3x3 on v (head slice), accumulated into o
    const int y = n / H_, x = n - y * H_;
#pragma unroll
    for (int ky = 0; ky < 3; ++ky) {
        const int yy = y + ky - 1;
        if (yy < 0 || yy >= H_) continue;
#pragma unroll
        for (int kx = 0; kx < 3; ++kx) {
            const int xx = x + kx - 1;
            if (xx < 0 || xx >= H_) continue;
            const int tap = ky * 3 + kx;
            const float* vp = &g_qkv[((size_t)(b * N_ + yy * H_ + xx)) * 1536 + 1024 + h * HD_];
#pragma unroll
            for (int i = 0; i < 16; ++i) {
                const float4 v4 = *(const float4*)(vp + 4 * i);
                o[i].x += v4.x * ws[4 * i + 0][tap];
                o[i].y += v4.y * ws[4 * i + 1][tap];
                o[i].z += v4.z * ws[4 * i + 2][tap];
                o[i].w += v4.w * ws[4 * i + 3][tap];
            }
        }
    }

    float* op = &g_out[((size_t)(b * N_ + n)) * C_ + h * HD_];
#pragma unroll
    for (int i = 0; i < 16; ++i) {
        float4 v;
        v.x = f2tf(o[i].x); v.y = f2tf(o[i].y); v.z = f2tf(o[i].z); v.w = f2tf(o[i].w);
        *(float4*)&op[4 * i] = v;
    }
}

// ---------------- launch ----------------
extern "C" void kernel_launch(void* const* d_in, const int* in_sizes, int n_in,
                              void* d_out, int out_size)
{
    const float* x      = (const float*)d_in[0];
    const float* qkv_w  = (const float*)d_in[1];
    const float* proj_w = (const float*)d_in[2];
    const float* proj_b = (const float*)d_in[3];
    const float* dwc_w  = (const float*)d_in[4];
    const float* dwc_b  = (const float*)d_in[5];
    float* out = (float*)d_out;

    float *p_qkv = nullptr, *p_out = nullptr, *p_w = nullptr;
    cudaGetSymbolAddress((void**)&p_qkv, g_qkv);
    cudaGetSymbolAddress((void**)&p_out, g_out);
    cudaGetSymbolAddress((void**)&p_w, g_w);

    cudaFuncSetAttribute(gemm_mma3, cudaFuncAttributeMaxDynamicSharedMemorySize, G3_SMEM);

    // 0. pre-convert inputs to tf32-rounded fp32 (x -> g_out scratch; weights -> g_w)
    cvt_tf32<<<(M_ * C_ / 4 + 255) / 256, 256>>>(x, p_out, M_ * C_ / 4);
    cvt_tf32<<<(1536 * 512 / 4 + 255) / 256, 256>>>(qkv_w, p_w, 1536 * 512 / 4);
    cvt_tf32<<<(512 * 512 / 4 + 255) / 256, 256>>>(proj_w, p_w + 1536 * 512, 512 * 512 / 4);

    // 1. QKV projection: [100352,512] @ [1536,512]^T -> g_qkv
    gemm_mma3<<<dim3(1536 / 128, M_ / 128), 256, G3_SMEM>>>(p_out, p_w, p_qkv, nullptr, 512, 512, 512, 1536);
    // 2. zero agent-attn accumulators
    zero_acc<<<(B_ * NH_ * ANUM_ * HD_ + 255) / 256, 256>>>();
    // 3. agent pooling
    pool_q<<<B_ * ANUM_, C_>>>();
    // 4. agent attention
    agent_kv<<<dim3(B_ * NH_, 7), 256>>>();
    // 5. normalize agent_v
    norm_av<<<B_ * NH_ * ANUM_, HD_>>>();
    // 6. q attention + fused dwc -> g_out (tf32-rounded)
    q_attn_dwc<<<dim3(B_ * NH_, (N_ + 127) / 128), 128>>>(dwc_w, dwc_b);
    // 7. output projection (+bias) -> d_out
    gemm_mma3<<<dim3(512 / 128, M_ / 128), 256, G3_SMEM>>>(p_out, p_w + 1536 * 512, out, proj_b, 512, 512, 512, 512);
}